// round 12
// baseline (speedup 1.0000x reference)
#include <cuda_runtime.h>
#include <cuda_bf16.h>
#include <cstdint>

// B=2, C=512, N=4096. out = x + Wo@Attn(GN(x)) + bo, [B,C,H,W] fp32.
// Folded formulation:
//   X  = lg2e*s * Wk^T Wq   (bf16)   u = ht @ X^T        (score projection)
//   cv = lg2e*s * Wk^T bq   (fp32)   d_j = cv . h_j       (column bias)
//   W' = Wo Wv              (bf16)   vv = W' h + b2       (value projection)
//   b2 = Wo bv              (fp32)
//   P~ = exp2(u_i.h_j + d_j); Z_i = sum_j P~
//   out[c,i] = x[c,i] + (sum_j vv[c,j] P~[i,j]) / Z_i + bo[c]
#define BATCH 2
#define CCH   512
#define NPIX  4096
#define GEPS  1e-6f

static const long long CN = (long long)CCH * NPIX;   // 2M
static const long long NN = (long long)NPIX * NPIX;  // 16M

// scratch (device globals)
__device__ __nv_bfloat16 g_ht[BATCH * NPIX * CCH];              // hT [B][pix][C]
__device__ __nv_bfloat16 g_u [BATCH * NPIX * CCH];              // u  [B][pix][C]
__device__ __nv_bfloat16 g_vv[BATCH * CCH * NPIX];              // vv [B][C][pix]
__device__ __nv_bfloat16 g_p [(long long)BATCH * NPIX * NPIX];  // exp scores bf16
__device__ __nv_bfloat16 g_X [CCH * CCH];                       // folded QK matrix
__device__ __nv_bfloat16 g_Wp[CCH * CCH];                       // W' = Wo Wv
__device__ float         g_b2[CCH];                             // Wo bv
__device__ float         g_cv[CCH];                             // lg2e*s*Wk^T bq
__device__ float         g_d [BATCH * NPIX];                    // column score bias
__device__ float         g_rowsum[BATCH * NPIX];
__device__ float         g_ssum4[BATCH * 32 * 4 * 2];           // GN partials

// ---------------------------------------------------------------------------
// PTX helpers
// ---------------------------------------------------------------------------
__device__ __forceinline__ void cpasync16(uint32_t s, const void* g) {
    asm volatile("cp.async.cg.shared.global [%0], [%1], 16;" :: "r"(s), "l"(g));
}
__device__ __forceinline__ uint32_t smem_u32(const void* p) {
    return (uint32_t)__cvta_generic_to_shared(p);
}
__device__ __forceinline__ void ldsm4(uint32_t r[4], uint32_t addr) {
    asm volatile("ldmatrix.sync.aligned.m8n8.x4.shared.b16 {%0,%1,%2,%3}, [%4];"
        : "=r"(r[0]), "=r"(r[1]), "=r"(r[2]), "=r"(r[3]) : "r"(addr));
}
__device__ __forceinline__ void mma_bf16(float c[4], const uint32_t a[4],
                                         const uint32_t b0, const uint32_t b1) {
    asm volatile(
        "mma.sync.aligned.m16n8k16.row.col.f32.bf16.bf16.f32 "
        "{%0,%1,%2,%3},{%4,%5,%6,%7},{%8,%9},{%0,%1,%2,%3};"
        : "+f"(c[0]), "+f"(c[1]), "+f"(c[2]), "+f"(c[3])
        : "r"(a[0]), "r"(a[1]), "r"(a[2]), "r"(a[3]), "r"(b0), "r"(b1));
}
__device__ __forceinline__ float ex2f(float x) {
    float y; asm("ex2.approx.ftz.f32 %0, %1;" : "=f"(y) : "f"(x));
    return y;
}

// ---------------------------------------------------------------------------
// bf16 tensor-core GEMM: D[M][N] = A[M][K] * B[N][K]^T (both row-major)
// Block 128x128x64, 256 thr = 8 warps (2x4), warp tile 64x32, m16n8k16,
// 3-stage cp.async, 2 CTAs/SM.
// EPI 0: bf16 out plain                                   (u)
// EPI 1: bf16 out + bias[m]                               (vv)
// EPI 2: exp2(acc + res_d[col]) bf16 + rowsum atomics     (S)
// EPI 3: fp32 out = acc/aux_rs[col] + bias[m] + res_x     (AV/final)
// ---------------------------------------------------------------------------
#define BM 128
#define BN 128
#define BK 64
#define ASTR 144
#define ASTAGE (BM * ASTR)
#define BSTAGE (BN * ASTR)
#define SMEM3 (3 * (ASTAGE + BSTAGE))   // 110592

template<int EPI>
__global__ __launch_bounds__(256, 2) void gemm_bf16_tc(
    const __nv_bfloat16* __restrict__ A, const __nv_bfloat16* __restrict__ B,
    void* __restrict__ Cv,
    const float* __restrict__ bias, const float* __restrict__ aux,
    const float* __restrict__ res,
    int K, int lda, int ldb, int ldc,
    long long sA, long long sB, long long sC, long long sAux, long long sR)
{
    extern __shared__ char smem[];
    const uint32_t sbA = smem_u32(smem);
    const uint32_t sbB = sbA + 3 * ASTAGE;

    const int tid  = threadIdx.x;
    const int wid  = tid >> 5;
    const int lane = tid & 31;
    const int g    = lane >> 2;
    const int tig  = lane & 3;
    const int sub  = lane >> 3;
    const int r8   = lane & 7;
    const int m_w  = (wid >> 2) * 64;
    const int n_w  = (wid & 3) * 32;
    const int m0   = blockIdx.y * BM;
    const int n0   = blockIdx.x * BN;
    const int z    = blockIdx.z;

    const __nv_bfloat16* Ab = A + (long long)z * sA + (long long)m0 * lda;
    const __nv_bfloat16* Bb = B + (long long)z * sB + (long long)n0 * ldb;

    float acc[4][4][4];
    #pragma unroll
    for (int i = 0; i < 4; i++)
        #pragma unroll
        for (int j = 0; j < 4; j++)
            #pragma unroll
            for (int r = 0; r < 4; r++) acc[i][j][r] = 0.f;

    const int nk = K / BK;

    auto load = [&](int ks, int buf) {
        const uint32_t ab = sbA + buf * ASTAGE;
        const uint32_t bb = sbB + buf * BSTAGE;
        #pragma unroll
        for (int it = 0; it < 4; it++) {
            int s = tid + it * 256;
            int r = s >> 3, c = s & 7;
            cpasync16(ab + r * ASTR + c * 16,
                      Ab + (long long)r * lda + ks * BK + c * 8);
        }
        #pragma unroll
        for (int it = 0; it < 4; it++) {
            int s = tid + it * 256;
            int r = s >> 3, c = s & 7;
            cpasync16(bb + r * ASTR + c * 16,
                      Bb + (long long)r * ldb + ks * BK + c * 8);
        }
        asm volatile("cp.async.commit_group;");
    };

    load(0, 0);
    if (nk > 1) load(1, 1);

    #pragma unroll 1
    for (int ks = 0; ks < nk; ks++) {
        const int buf = ks % 3;
        if (ks + 1 < nk) asm volatile("cp.async.wait_group 1;");
        else             asm volatile("cp.async.wait_group 0;");
        __syncthreads();
        if (ks + 2 < nk) load(ks + 2, (ks + 2) % 3);

        const uint32_t ab = sbA + buf * ASTAGE;
        const uint32_t bb = sbB + buf * BSTAGE;

        #pragma unroll
        for (int kk = 0; kk < 4; kk++) {
            uint32_t af[4][4];
            #pragma unroll
            for (int i = 0; i < 4; i++) {
                uint32_t addr = ab + (m_w + 16 * i + (sub & 1) * 8 + r8) * ASTR
                              + kk * 32 + (sub >> 1) * 16;
                ldsm4(af[i], addr);
            }
            uint32_t bf[4][2];
            #pragma unroll
            for (int jj = 0; jj < 2; jj++) {
                uint32_t t[4];
                uint32_t addr = bb + (n_w + 16 * jj + (sub >> 1) * 8 + r8) * ASTR
                              + kk * 32 + (sub & 1) * 16;
                ldsm4(t, addr);
                bf[2 * jj][0] = t[0]; bf[2 * jj][1] = t[1];
                bf[2 * jj + 1][0] = t[2]; bf[2 * jj + 1][1] = t[3];
            }
            #pragma unroll
            for (int i = 0; i < 4; i++)
                #pragma unroll
                for (int j = 0; j < 4; j++)
                    mma_bf16(acc[i][j], af[i], bf[j][0], bf[j][1]);
        }
    }

    // ------------------------------ epilogues ------------------------------
    if (EPI == 0) {           // plain bf16
        __nv_bfloat16* C = (__nv_bfloat16*)Cv + (long long)z * sC;
        #pragma unroll
        for (int i = 0; i < 4; i++) {
            int r0 = m0 + m_w + 16 * i + g, r1 = r0 + 8;
            #pragma unroll
            for (int j = 0; j < 4; j++) {
                int col = n0 + n_w + 8 * j + 2 * tig;
                *(__nv_bfloat162*)&C[(long long)r0 * ldc + col] =
                    __float22bfloat162_rn(make_float2(acc[i][j][0], acc[i][j][1]));
                *(__nv_bfloat162*)&C[(long long)r1 * ldc + col] =
                    __float22bfloat162_rn(make_float2(acc[i][j][2], acc[i][j][3]));
            }
        }
    } else if (EPI == 1) {    // bf16 + bias[m]
        __nv_bfloat16* C = (__nv_bfloat16*)Cv + (long long)z * sC;
        #pragma unroll
        for (int i = 0; i < 4; i++) {
            int r0 = m0 + m_w + 16 * i + g, r1 = r0 + 8;
            float bm0 = bias[r0], bm1 = bias[r1];
            #pragma unroll
            for (int j = 0; j < 4; j++) {
                int col = n0 + n_w + 8 * j + 2 * tig;
                *(__nv_bfloat162*)&C[(long long)r0 * ldc + col] =
                    __float22bfloat162_rn(make_float2(acc[i][j][0] + bm0,
                                                      acc[i][j][1] + bm0));
                *(__nv_bfloat162*)&C[(long long)r1 * ldc + col] =
                    __float22bfloat162_rn(make_float2(acc[i][j][2] + bm1,
                                                      acc[i][j][3] + bm1));
            }
        }
    } else if (EPI == 2) {    // exp2(acc + d[col]), rowsum atomics
        __nv_bfloat16* C = (__nv_bfloat16*)Cv + (long long)z * sC;
        float* rs = (float*)aux + (long long)z * sAux;
        const float* dv = res + (long long)z * sR;
        #pragma unroll
        for (int i = 0; i < 4; i++) {
            int r0 = m0 + m_w + 16 * i + g, r1 = r0 + 8;
            float s0 = 0.f, s1 = 0.f;
            #pragma unroll
            for (int j = 0; j < 4; j++) {
                int col = n0 + n_w + 8 * j + 2 * tig;
                float d0 = dv[col], d1 = dv[col + 1];
                float e0 = ex2f(acc[i][j][0] + d0);
                float e1 = ex2f(acc[i][j][1] + d1);
                float e2 = ex2f(acc[i][j][2] + d0);
                float e3 = ex2f(acc[i][j][3] + d1);
                s0 += e0 + e1; s1 += e2 + e3;
                *(__nv_bfloat162*)&C[(long long)r0 * ldc + col] =
                    __float22bfloat162_rn(make_float2(e0, e1));
                *(__nv_bfloat162*)&C[(long long)r1 * ldc + col] =
                    __float22bfloat162_rn(make_float2(e2, e3));
            }
            s0 += __shfl_xor_sync(0xffffffffu, s0, 1);
            s0 += __shfl_xor_sync(0xffffffffu, s0, 2);
            s1 += __shfl_xor_sync(0xffffffffu, s1, 1);
            s1 += __shfl_xor_sync(0xffffffffu, s1, 2);
            if (tig == 0) {
                atomicAdd(&rs[r0], s0);
                atomicAdd(&rs[r1], s1);
            }
        }
    } else {                  // EPI 3: fp32 = acc/rs[col] + bias[m] + x
        float* C = (float*)Cv + (long long)z * sC;
        const float* rs = aux + (long long)z * sAux;
        const float* xr = res + (long long)z * sR;
        #pragma unroll
        for (int i = 0; i < 4; i++) {
            int r0 = m0 + m_w + 16 * i + g, r1 = r0 + 8;
            float bm0 = bias[r0], bm1 = bias[r1];
            #pragma unroll
            for (int j = 0; j < 4; j++) {
                int col = n0 + n_w + 8 * j + 2 * tig;
                float i0 = 1.f / rs[col], i1 = 1.f / rs[col + 1];
                long long o0 = (long long)r0 * ldc + col;
                long long o1 = (long long)r1 * ldc + col;
                float2 x0 = *(const float2*)&xr[o0];
                float2 x1 = *(const float2*)&xr[o1];
                float2 v0 = make_float2(acc[i][j][0] * i0 + bm0 + x0.x,
                                        acc[i][j][1] * i1 + bm0 + x0.y);
                float2 v1 = make_float2(acc[i][j][2] * i0 + bm1 + x1.x,
                                        acc[i][j][3] * i1 + bm1 + x1.y);
                *(float2*)&C[o0] = v0;
                *(float2*)&C[o1] = v1;
            }
        }
    }
}

// ---------------------------------------------------------------------------
// Fused prologue: weight folds + bias folds + GN partial stats + zeroing.
// Ranges: [0,256) X-fold | [256,512) W'-fold | [512,516) b2/cvec |
//         [516,772) GN stats | [772,836) zero rowsum+d
// ---------------------------------------------------------------------------
#define FX0 0
#define FW0 256
#define FB0 512
#define FS0 516
#define FZ0 772
#define PRO_BLOCKS 836

__global__ __launch_bounds__(256) void prologue_kernel(
    const float* __restrict__ x,
    const float* __restrict__ wq, const float* __restrict__ wk,
    const float* __restrict__ wv, const float* __restrict__ wo,
    const float* __restrict__ bq, const float* __restrict__ bv,
    __nv_bfloat16* __restrict__ X, __nv_bfloat16* __restrict__ Wp,
    float* __restrict__ b2, float* __restrict__ cv,
    float* __restrict__ ssum4, float* __restrict__ rowsum,
    float* __restrict__ dvec)
{
    const int blk = blockIdx.x;
    const int t = threadIdx.x;
    const float qs = 0.044194173824159216f * 1.4426950408889634f;  // s*lg2e

    if (blk < FW0) {
        // X[c][c'] = qs * sum_co wk[co][c] * wq[co][c']
        const int cb  = (blk >> 4) * 32;
        const int cpb = (blk & 15) * 32;
        __shared__ float sk[32][33], sq[32][33];
        float a00 = 0, a01 = 0, a10 = 0, a11 = 0;
        const int a = (t >> 4) * 2, b = (t & 15) * 2;
        for (int co0 = 0; co0 < 512; co0 += 32) {
            #pragma unroll
            for (int it = 0; it < 4; it++) {
                int idx = t + it * 256; int r = idx >> 5, cc = idx & 31;
                sk[r][cc] = wk[(co0 + r) * 512 + cb + cc];
                sq[r][cc] = wq[(co0 + r) * 512 + cpb + cc];
            }
            __syncthreads();
            #pragma unroll 8
            for (int r = 0; r < 32; r++) {
                float k0 = sk[r][a], k1 = sk[r][a + 1];
                float q0 = sq[r][b], q1 = sq[r][b + 1];
                a00 += k0 * q0; a01 += k0 * q1;
                a10 += k1 * q0; a11 += k1 * q1;
            }
            __syncthreads();
        }
        X[(cb + a) * 512 + cpb + b]         = __float2bfloat16_rn(qs * a00);
        X[(cb + a) * 512 + cpb + b + 1]     = __float2bfloat16_rn(qs * a01);
        X[(cb + a + 1) * 512 + cpb + b]     = __float2bfloat16_rn(qs * a10);
        X[(cb + a + 1) * 512 + cpb + b + 1] = __float2bfloat16_rn(qs * a11);
    } else if (blk < FB0) {
        // W'[c][c'] = sum_co wo[c][co] * wv[co][c']
        const int tb = blk - FW0;
        const int cb  = (tb >> 4) * 32;
        const int cpb = (tb & 15) * 32;
        __shared__ float sa[32][33], sv[32][33];
        float a00 = 0, a01 = 0, a10 = 0, a11 = 0;
        const int a = (t >> 4) * 2, b = (t & 15) * 2;
        for (int co0 = 0; co0 < 512; co0 += 32) {
            #pragma unroll
            for (int it = 0; it < 4; it++) {
                int idx = t + it * 256; int r = idx >> 5, cc = idx & 31;
                sa[r][cc] = wo[(cb + r) * 512 + co0 + cc];   // sa[row c][co]
                sv[r][cc] = wv[(co0 + r) * 512 + cpb + cc];
            }
            __syncthreads();
            #pragma unroll 8
            for (int r = 0; r < 32; r++) {
                float o0 = sa[a][r], o1 = sa[a + 1][r];
                float v0 = sv[r][b], v1 = sv[r][b + 1];
                a00 += o0 * v0; a01 += o0 * v1;
                a10 += o1 * v0; a11 += o1 * v1;
            }
            __syncthreads();
        }
        Wp[(cb + a) * 512 + cpb + b]         = __float2bfloat16_rn(a00);
        Wp[(cb + a) * 512 + cpb + b + 1]     = __float2bfloat16_rn(a01);
        Wp[(cb + a + 1) * 512 + cpb + b]     = __float2bfloat16_rn(a10);
        Wp[(cb + a + 1) * 512 + cpb + b + 1] = __float2bfloat16_rn(a11);
    } else if (blk < FS0) {
        const int sel = blk - FB0;    // 0,1: b2; 2,3: cvec
        if (sel < 2) {
            int c = sel * 256 + t;
            float s = 0.f;
            for (int co = 0; co < 512; co++) s += wo[c * 512 + co] * bv[co];
            b2[c] = s;
        } else {
            int ci = (sel - 2) * 256 + t;
            float s = 0.f;
            for (int co = 0; co < 512; co++) s += wk[co * 512 + ci] * bq[co];
            cv[ci] = qs * s;
        }
    } else if (blk < FZ0) {
        // GN partial stats
        const int pb = blk - FS0;
        const long long base = (long long)(pb >> 2) * 65536 + (pb & 3) * 16384;
        float s = 0.f, ss = 0.f;
        #pragma unroll 4
        for (int i = t; i < 16384; i += 256) {
            float v = x[base + i];
            s += v; ss += v * v;
        }
        #pragma unroll
        for (int off = 16; off; off >>= 1) {
            s  += __shfl_down_sync(0xffffffffu, s,  off);
            ss += __shfl_down_sync(0xffffffffu, ss, off);
        }
        __shared__ float shs[8], shss[8];
        int wid = t >> 5, lane = t & 31;
        if (lane == 0) { shs[wid] = s; shss[wid] = ss; }
        __syncthreads();
        if (t == 0) {
            float ts = 0.f, tss = 0.f;
            #pragma unroll
            for (int i = 0; i < 8; i++) { ts += shs[i]; tss += shss[i]; }
            ssum4[2 * pb]     = ts;
            ssum4[2 * pb + 1] = tss;
        }
    } else {
        int idx = (blk - FZ0) * 256 + t;   // 0..16383
        if (idx < BATCH * NPIX) rowsum[idx] = 0.f;
        else                    dvec[idx - BATCH * NPIX] = 0.f;
    }
}

// ---------------------------------------------------------------------------
// GN apply + transpose (bf16 out) + d accumulation (d_j += cv . h_j)
// ---------------------------------------------------------------------------
__global__ __launch_bounds__(256) void gn_apply_t_kernel(
    const float* __restrict__ x, const float* __restrict__ w,
    const float* __restrict__ b, const float* __restrict__ ssum4,
    const float* __restrict__ cv,
    __nv_bfloat16* __restrict__ ht, float* __restrict__ dvec)
{
    __shared__ float tile[32][33];
    const int p0 = blockIdx.x * 32;
    const int c0 = blockIdx.y * 32;
    const int bb = blockIdx.z;
    const int tx = threadIdx.x, ty = threadIdx.y;   // (32, 8)
    const long long xb = (long long)bb * CN;

    #pragma unroll
    for (int r = 0; r < 4; r++) {
        int cl = ty + 8 * r;
        tile[cl][tx] = x[xb + (long long)(c0 + cl) * NPIX + p0 + tx];
    }
    __syncthreads();
    const int c = c0 + tx;
    const int gidx = c >> 4;
    const int bg = bb * 32 + gidx;
    float ts = 0.f, tss = 0.f;
    #pragma unroll
    for (int pp = 0; pp < 4; pp++) {
        ts  += ssum4[2 * (bg * 4 + pp)];
        tss += ssum4[2 * (bg * 4 + pp) + 1];
    }
    const float mean = ts * (1.f / 65536.f);
    const float var  = tss * (1.f / 65536.f) - mean * mean;
    const float rstd = rsqrtf(var + GEPS);
    const float sc = rstd * w[c];
    const float sh = b[c] - mean * sc;
    const float cvc = cv[c];
    #pragma unroll
    for (int r = 0; r < 4; r++) {
        int pl = ty + 8 * r;
        float v = tile[tx][pl] * sc + sh;
        ht[xb + (long long)(p0 + pl) * CCH + c] = __float2bfloat16_rn(v);
        float contrib = cvc * v;
        #pragma unroll
        for (int off = 16; off; off >>= 1)
            contrib += __shfl_down_sync(0xffffffffu, contrib, off);
        if (tx == 0)
            atomicAdd(&dvec[bb * NPIX + p0 + pl], contrib);
    }
}

// ---------------------------------------------------------------------------
extern "C" void kernel_launch(void* const* d_in, const int* in_sizes, int n_in,
                              void* d_out, int out_size)
{
    const float* x    = (const float*)d_in[0];
    const float* gn_w = (const float*)d_in[1];
    const float* gn_b = (const float*)d_in[2];
    const float* wq   = (const float*)d_in[3];
    const float* bq   = (const float*)d_in[4];
    const float* wk   = (const float*)d_in[5];
    const float* bk   = (const float*)d_in[6];  // cancels in softmax
    const float* wv   = (const float*)d_in[7];
    const float* bv   = (const float*)d_in[8];
    const float* wo   = (const float*)d_in[9];
    const float* bo   = (const float*)d_in[10];
    float* out = (float*)d_out;
    (void)bk;

    __nv_bfloat16 *ht, *u, *vv, *p, *X, *Wp;
    float *b2, *cv, *dvec, *rowsum, *ssum4;
    cudaGetSymbolAddress((void**)&ht,     g_ht);
    cudaGetSymbolAddress((void**)&u,      g_u);
    cudaGetSymbolAddress((void**)&vv,     g_vv);
    cudaGetSymbolAddress((void**)&p,      g_p);
    cudaGetSymbolAddress((void**)&X,      g_X);
    cudaGetSymbolAddress((void**)&Wp,     g_Wp);
    cudaGetSymbolAddress((void**)&b2,     g_b2);
    cudaGetSymbolAddress((void**)&cv,     g_cv);
    cudaGetSymbolAddress((void**)&dvec,   g_d);
    cudaGetSymbolAddress((void**)&rowsum, g_rowsum);
    cudaGetSymbolAddress((void**)&ssum4,  g_ssum4);

    cudaFuncSetAttribute(gemm_bf16_tc<0>,
        cudaFuncAttributeMaxDynamicSharedMemorySize, SMEM3);
    cudaFuncSetAttribute(gemm_bf16_tc<1>,
        cudaFuncAttributeMaxDynamicSharedMemorySize, SMEM3);
    cudaFuncSetAttribute(gemm_bf16_tc<2>,
        cudaFuncAttributeMaxDynamicSharedMemorySize, SMEM3);
    cudaFuncSetAttribute(gemm_bf16_tc<3>,
        cudaFuncAttributeMaxDynamicSharedMemorySize, SMEM3);

    // 0) prologue: folds + stats + zeroing (one launch)
    prologue_kernel<<<PRO_BLOCKS, 256>>>(
        x, wq, wk, wv, wo, bq, bv, X, Wp, b2, cv, ssum4, rowsum, dvec);

    // 1) GN apply + transpose + d accumulation
    gn_apply_t_kernel<<<dim3(NPIX / 32, CCH / 32, BATCH), dim3(32, 8)>>>(
        x, gn_w, gn_b, ssum4, cv, ht, dvec);

    // 2) u = ht @ X^T   (M=4096, N=512, K=512)
    dim3 gU(CCH / BN, NPIX / BM, BATCH);
    gemm_bf16_tc<0><<<gU, 256, SMEM3>>>(
        ht, X, u, nullptr, nullptr, nullptr,
        CCH, CCH, CCH, CCH, CN, 0, CN, 0, 0);

    // 3) vv = W' @ ht^T + b2[m]   (M=512, N=4096, K=512)
    dim3 gV(NPIX / BN, CCH / BM, BATCH);
    gemm_bf16_tc<1><<<gV, 256, SMEM3>>>(
        Wp, ht, vv, b2, nullptr, nullptr,
        CCH, CCH, CCH, NPIX, 0, CN, CN, 0, 0);

    // 4) P~ = exp2(u @ ht^T + d[col]) -> bf16, rowsum accumulated
    dim3 gS(NPIX / BN, NPIX / BM, BATCH);
    gemm_bf16_tc<2><<<gS, 256, SMEM3>>>(
        u, ht, p, nullptr, rowsum, dvec,
        CCH, CCH, CCH, NPIX, CN, CN, NN, NPIX, NPIX);

    // 5) out = x + (vv @ P~^T)/rowsum[col] + bo[m]   (M=512, N=4096, K=4096)
    dim3 gAV(NPIX / BN, CCH / BM, BATCH);
    gemm_bf16_tc<3><<<gAV, 256, SMEM3>>>(
        vv, p, out, bo, rowsum, x,
        NPIX, NPIX, NPIX, NPIX, CN, NN, CN, NPIX, CN);
}